// round 7
// baseline (speedup 1.0000x reference)
#include <cuda_runtime.h>

// Fixed problem constants:
//   x: (4,1,128,2048) f32 ; vals: 16.7M f32 ; rows/cols: 16.7M int32-or-int64 (rows sorted)
//   out: (4,1,512,256) f32 = 524288 elements
#define NNZ_TOTAL   16777216
#define NCOLS       262144      // NS*NC = 2048*128
#define OUT_ELEMS   524288
#define OUT_PLANE   131072      // per-bk output plane (Nz*Nx)
#define TOTAL_WARPS 8192
#define NNZ_PER_WARP (NNZ_TOTAL / TOTAL_WARPS)   // 2048
#define GROUPS       (NNZ_PER_WARP / 32)         // 64

// Scratch: transposed RHS, rhs_t[col] = {x[0,c,s], x[1,c,s], x[2,c,s], x[3,c,s]}, col = s*128 + c
static __device__ float4  g_rhs[NCOLS];          // 4 MB, L2-resident during main kernel
static __device__ unsigned g_stride;             // 2 if indices are int64, 1 if int32

// --- fused prep: dtype probe + zero output + build transposed RHS -------------
__global__ void k_prep(const float* __restrict__ x,
                       const unsigned* __restrict__ rows_u32,
                       float* __restrict__ out) {
    unsigned gid = blockIdx.x * blockDim.x + threadIdx.x;   // < 524288
    if (gid == 0) g_stride = (rows_u32[NNZ_TOTAL - 1] == 0u) ? 2u : 1u;
    out[gid] = 0.0f;                                        // d_out is poisoned 0xAA
    if (gid < NCOLS) {
        unsigned c = gid & 127u;
        unsigned s = gid >> 7;
        unsigned o = c * 2048u + s;
        float4 v;
        v.x = x[o];
        v.y = x[o + 262144u];
        v.z = x[o + 524288u];
        v.w = x[o + 786432u];
        g_rhs[gid] = v;
    }
}

// --- flush one completed row: butterfly reduce + 4 atomics (cold path) ---------
__device__ __forceinline__ void flush_row(unsigned row,
                                          float a0, float a1, float a2, float a3,
                                          unsigned lane,
                                          float* __restrict__ out) {
    #pragma unroll
    for (int d = 16; d > 0; d >>= 1) {
        a0 += __shfl_xor_sync(0xffffffffu, a0, d);
        a1 += __shfl_xor_sync(0xffffffffu, a1, d);
        a2 += __shfl_xor_sync(0xffffffffu, a2, d);
        a3 += __shfl_xor_sync(0xffffffffu, a3, d);
    }
    if (lane < 4u) {
        float s = (lane == 0u) ? a0 : (lane == 1u) ? a1 : (lane == 2u) ? a2 : a3;
        // out layout: bk*131072 + z*256 + x, with row r = x*512 + z
        unsigned o = (row & 511u) * 256u + (row >> 9);
        atomicAdd(out + lane * OUT_PLANE + o, s);
    }
}

// --- process one 32-nnz group (rows sorted within and across groups) -----------
__device__ __forceinline__ void process_group(float v, unsigned row, float4 r,
                                              unsigned& cur_row,
                                              float& a0, float& a1, float& a2, float& a3,
                                              unsigned lane,
                                              float* __restrict__ out) {
    float c0 = v * r.x, c1 = v * r.y, c2 = v * r.z, c3 = v * r.w;
    if (__all_sync(0xffffffffu, row == cur_row)) {           // fast path (~75%)
        a0 += c0; a1 += c1; a2 += c2; a3 += c3;
    } else {                                                 // row boundary in group
        unsigned r31 = __shfl_sync(0xffffffffu, row, 31);
        bool mine = (row == cur_row);                        // sorted -> prefix lanes
        if (mine) { a0 += c0; a1 += c1; a2 += c2; a3 += c3; }
        flush_row(cur_row, a0, a1, a2, a3, lane, out);
        if (!mine && row != r31) {
            // row fully contained inside this group (needs <32 nnz): direct atomics
            unsigned o = (row & 511u) * 256u + (row >> 9);
            atomicAdd(out + o,                  c0);
            atomicAdd(out + OUT_PLANE + o,      c1);
            atomicAdd(out + 2u * OUT_PLANE + o, c2);
            atomicAdd(out + 3u * OUT_PLANE + o, c3);
        }
        bool last = (row == r31);                            // suffix lanes: new row
        a0 = last ? c0 : 0.f;
        a1 = last ? c1 : 0.f;
        a2 = last ? c2 : 0.f;
        a3 = last ? c3 : 0.f;
        cur_row = r31;
    }
}

// --- main SpMM: R3 shape (depth-1, 2 live float4s) + split col->gather chain ----
// cols prefetched TWO groups ahead, gather ONE group ahead, single loop, no
// unroll -> same register footprint as the 77us version but no serialized
// 2x-L2-latency dependency inside one iteration window.
__global__ void __launch_bounds__(256, 8)
k_spmm(const float* __restrict__ vals,
       const unsigned* __restrict__ rows_u32,
       const unsigned* __restrict__ cols_u32,
       float* __restrict__ out) {
    const unsigned warp_id = (blockIdx.x * blockDim.x + threadIdx.x) >> 5;
    const unsigned lane    = threadIdx.x & 31u;
    const unsigned st      = g_stride;          // 1 (int32) or 2 (int64, read low word)
    const unsigned rstep   = st * 32u;
    unsigned i = warp_id * NNZ_PER_WARP + lane; // element index of current group

    const float*    vp = vals     + i;
    const unsigned* rp = rows_u32 + st * i;
    const unsigned* cp = cols_u32 + st * i;

    // prologue: group 0 full; group 1 col only
    unsigned colB = cp[0];                      // col for group 0
    unsigned colC = cp[rstep];                  // col for group 1
    float4   gA   = g_rhs[colB];                // gather group 0
    float    v    = vp[0];
    unsigned row  = rp[0];
    colB = colC;

    unsigned cur_row = __shfl_sync(0xffffffffu, row, 0);
    float a0 = 0.f, a1 = 0.f, a2 = 0.f, a3 = 0.f;

    #pragma unroll 1
    for (int g = 0; g < GROUPS - 2; ++g) {
        colC = cp[2u * rstep];                  // col, group g+2 (2 ahead)
        float4   gB   = g_rhs[colB];            // gather, group g+1 (col arrived)
        float    vn   = vp[32];                 // streams, group g+1
        unsigned rown = rp[rstep];
        vp += 32u; rp += rstep; cp += rstep;

        process_group(v, row, gA, cur_row, a0, a1, a2, a3, lane, out);

        colB = colC; gA = gB; v = vn; row = rown;
    }

    // epilogue: groups GROUPS-2 (state in gA/v/row) and GROUPS-1 (col in colB)
    {
        float4   gB   = g_rhs[colB];
        float    vn   = vp[32];
        unsigned rown = rp[rstep];
        process_group(v,  row,  gA, cur_row, a0, a1, a2, a3, lane, out);
        process_group(vn, rown, gB, cur_row, a0, a1, a2, a3, lane, out);
    }
    flush_row(cur_row, a0, a1, a2, a3, lane, out);
}

extern "C" void kernel_launch(void* const* d_in, const int* in_sizes, int n_in,
                              void* d_out, int out_size) {
    const float*    x    = (const float*)d_in[0];
    const float*    vals = (const float*)d_in[1];
    const unsigned* rows = (const unsigned*)d_in[2];
    const unsigned* cols = (const unsigned*)d_in[3];
    float*          out  = (float*)d_out;

    k_prep<<<OUT_ELEMS / 256, 256>>>(x, rows, out);
    k_spmm<<<TOTAL_WARPS * 32 / 256, 256>>>(vals, rows, cols, out);
}

// round 8
// speedup vs baseline: 1.0503x; 1.0503x over previous
#include <cuda_runtime.h>

// Fixed problem constants:
//   x: (4,1,128,2048) f32 ; vals: 16.7M f32 ; rows/cols: 16.7M int32-or-int64 (rows sorted)
//   out: (4,1,512,256) f32 = 524288 elements
#define NNZ_TOTAL   16777216
#define NCOLS       262144      // NS*NC = 2048*128
#define OUT_ELEMS   524288
#define OUT_PLANE   131072      // per-bk output plane (Nz*Nx)
#define GROUPS_TOTAL 524288     // NNZ / 32
#define NUM_BLOCKS   2368       // 148 SMs x 16 blocks -> exactly 2 full waves at 8 blocks/SM
#define WARPS_TOTAL  (NUM_BLOCKS * 8)   // 18944 warps, 27-28 groups each

// Scratch: transposed RHS, rhs_t[col] = {x[0,c,s], x[1,c,s], x[2,c,s], x[3,c,s]}, col = s*128 + c
static __device__ float4  g_rhs[NCOLS];          // 4 MB, L2-resident during main kernel
static __device__ unsigned g_stride;             // 2 if indices are int64, 1 if int32

// --- fused prep: dtype probe + zero output + build transposed RHS -------------
__global__ void k_prep(const float* __restrict__ x,
                       const unsigned* __restrict__ rows_u32,
                       float* __restrict__ out) {
    unsigned gid = blockIdx.x * blockDim.x + threadIdx.x;   // < 524288
    if (gid == 0) g_stride = (rows_u32[NNZ_TOTAL - 1] == 0u) ? 2u : 1u;
    out[gid] = 0.0f;                                        // d_out is poisoned 0xAA
    if (gid < NCOLS) {
        unsigned c = gid & 127u;
        unsigned s = gid >> 7;
        unsigned o = c * 2048u + s;
        float4 v;
        v.x = x[o];
        v.y = x[o + 262144u];
        v.z = x[o + 524288u];
        v.w = x[o + 786432u];
        g_rhs[gid] = v;
    }
}

// --- flush one completed row: butterfly reduce + 4 atomics (cold path) ---------
__device__ __forceinline__ void flush_row(unsigned row,
                                          float a0, float a1, float a2, float a3,
                                          unsigned lane,
                                          float* __restrict__ out) {
    #pragma unroll
    for (int d = 16; d > 0; d >>= 1) {
        a0 += __shfl_xor_sync(0xffffffffu, a0, d);
        a1 += __shfl_xor_sync(0xffffffffu, a1, d);
        a2 += __shfl_xor_sync(0xffffffffu, a2, d);
        a3 += __shfl_xor_sync(0xffffffffu, a3, d);
    }
    if (lane < 4u) {
        float s = (lane == 0u) ? a0 : (lane == 1u) ? a1 : (lane == 2u) ? a2 : a3;
        // out layout: bk*131072 + z*256 + x, with row r = x*512 + z
        unsigned o = (row & 511u) * 256u + (row >> 9);
        atomicAdd(out + lane * OUT_PLANE + o, s);
    }
}

// --- main SpMM: R3 inner loop (depth-1 pipeline, 32 regs) + balanced grid ------
// grid = 148x16 blocks -> exactly two 100%-filled residency waves. Each warp
// takes a computed contiguous group range [start,end) (27-28 groups), so the
// sorted-row fast path and flush rate are unchanged while per-SM work spread
// drops from 14% to ~3.7%.
__global__ void __launch_bounds__(256)
k_spmm(const float* __restrict__ vals,
       const unsigned* __restrict__ rows_u32,
       const unsigned* __restrict__ cols_u32,
       float* __restrict__ out) {
    const unsigned warp_id = (blockIdx.x * blockDim.x + threadIdx.x) >> 5;
    const unsigned lane    = threadIdx.x & 31u;
    const unsigned st      = g_stride;          // 1 (int32) or 2 (int64, read low word)
    const unsigned rstep   = st * 32u;

    // contiguous group range for this warp (64-bit math; 27 or 28 groups)
    const unsigned g0 = (unsigned)(((unsigned long long)warp_id * GROUPS_TOTAL) / WARPS_TOTAL);
    const unsigned g1 = (unsigned)(((unsigned long long)(warp_id + 1u) * GROUPS_TOTAL) / WARPS_TOTAL);
    const int      n  = (int)(g1 - g0);

    const unsigned  e0 = g0 * 32u + lane;       // first element index
    const float*    vp = vals     + e0;
    const unsigned* rp = rows_u32 + st * e0;
    const unsigned* cp = cols_u32 + st * e0;

    // pipeline stage 0
    float    v   = *vp;
    unsigned row = *rp;
    unsigned col = *cp;
    float4   r   = g_rhs[col];

    unsigned cur_row = __shfl_sync(0xffffffffu, row, 0);
    float a0 = 0.f, a1 = 0.f, a2 = 0.f, a3 = 0.f;

    #pragma unroll 1
    for (int it = 0; it < n - 1; ++it) {
        // prefetch next group (hides gather latency behind the logic below)
        vp += 32u; rp += rstep; cp += rstep;
        float    vn   = *vp;
        unsigned rown = *rp;
        unsigned coln = *cp;
        float4   rn   = g_rhs[coln];

        float c0 = v * r.x, c1 = v * r.y, c2 = v * r.z, c3 = v * r.w;
        if (__all_sync(0xffffffffu, row == cur_row)) {       // fast path (~75%)
            a0 += c0; a1 += c1; a2 += c2; a3 += c3;
        } else {                                             // row boundary in group
            unsigned r31 = __shfl_sync(0xffffffffu, row, 31);
            bool mine = (row == cur_row);                    // sorted -> prefix lanes
            if (mine) { a0 += c0; a1 += c1; a2 += c2; a3 += c3; }
            flush_row(cur_row, a0, a1, a2, a3, lane, out);
            if (!mine && row != r31) {
                // row fully contained inside this group (needs <32 nnz): direct atomics
                unsigned o = (row & 511u) * 256u + (row >> 9);
                atomicAdd(out + o,                  c0);
                atomicAdd(out + OUT_PLANE + o,      c1);
                atomicAdd(out + 2u * OUT_PLANE + o, c2);
                atomicAdd(out + 3u * OUT_PLANE + o, c3);
            }
            bool last = (row == r31);                        // suffix lanes: new row
            a0 = last ? c0 : 0.f;
            a1 = last ? c1 : 0.f;
            a2 = last ? c2 : 0.f;
            a3 = last ? c3 : 0.f;
            cur_row = r31;
        }
        v = vn; row = rown; r = rn;
    }

    // epilogue: process final group
    {
        float c0 = v * r.x, c1 = v * r.y, c2 = v * r.z, c3 = v * r.w;
        if (__all_sync(0xffffffffu, row == cur_row)) {
            a0 += c0; a1 += c1; a2 += c2; a3 += c3;
        } else {
            unsigned r31 = __shfl_sync(0xffffffffu, row, 31);
            bool mine = (row == cur_row);
            if (mine) { a0 += c0; a1 += c1; a2 += c2; a3 += c3; }
            flush_row(cur_row, a0, a1, a2, a3, lane, out);
            if (!mine && row != r31) {
                unsigned o = (row & 511u) * 256u + (row >> 9);
                atomicAdd(out + o,                  c0);
                atomicAdd(out + OUT_PLANE + o,      c1);
                atomicAdd(out + 2u * OUT_PLANE + o, c2);
                atomicAdd(out + 3u * OUT_PLANE + o, c3);
            }
            bool last = (row == r31);
            a0 = last ? c0 : 0.f;
            a1 = last ? c1 : 0.f;
            a2 = last ? c2 : 0.f;
            a3 = last ? c3 : 0.f;
            cur_row = r31;
        }
    }
    flush_row(cur_row, a0, a1, a2, a3, lane, out);
}

extern "C" void kernel_launch(void* const* d_in, const int* in_sizes, int n_in,
                              void* d_out, int out_size) {
    const float*    x    = (const float*)d_in[0];
    const float*    vals = (const float*)d_in[1];
    const unsigned* rows = (const unsigned*)d_in[2];
    const unsigned* cols = (const unsigned*)d_in[3];
    float*          out  = (float*)d_out;

    k_prep<<<OUT_ELEMS / 256, 256>>>(x, rows, out);
    k_spmm<<<NUM_BLOCKS, 256>>>(vals, rows, cols, out);
}

// round 10
// speedup vs baseline: 1.0754x; 1.0239x over previous
#include <cuda_runtime.h>

// Fixed problem constants:
//   x: (4,1,128,2048) f32 ; vals: 16.7M f32 ; rows/cols: 16.7M int32-or-int64 (rows sorted)
//   out: (4,1,512,256) f32 = 524288 elements
#define NNZ_TOTAL   16777216
#define NCOLS       262144      // NS*NC = 2048*128
#define OUT_ELEMS   524288
#define OUT_PLANE   131072      // per-bk output plane (Nz*Nx)
#define TOTAL_WARPS 8192
#define NNZ_PER_WARP (NNZ_TOTAL / TOTAL_WARPS)   // 2048
#define ITERS        (NNZ_PER_WARP / 32)         // 64

// Scratch: transposed RHS, rhs_t[col] = {x[0,c,s], x[1,c,s], x[2,c,s], x[3,c,s]}, col = s*128 + c
static __device__ float4  g_rhs[NCOLS];          // 4 MB, L2-resident during main kernel
static __device__ unsigned g_stride;             // 2 if indices are int64, 1 if int32

// --- fused prep: dtype probe + zero output + build transposed RHS -------------
// dtype probe: word [NNZ-1] (u32 view) is in-bounds for both layouts:
//   int64: HIGH half of element (NNZ-2)/2 -> always 0 ; int32: last sorted row != 0
__global__ void k_prep(const float* __restrict__ x,
                       const unsigned* __restrict__ rows_u32,
                       float* __restrict__ out) {
    unsigned gid = blockIdx.x * blockDim.x + threadIdx.x;   // < 524288
    if (gid == 0) g_stride = (rows_u32[NNZ_TOTAL - 1] == 0u) ? 2u : 1u;
    out[gid] = 0.0f;                                        // d_out is poisoned 0xAA
    if (gid < NCOLS) {
        unsigned c = gid & 127u;
        unsigned s = gid >> 7;
        unsigned o = c * 2048u + s;
        float4 v;
        v.x = x[o];
        v.y = x[o + 262144u];
        v.z = x[o + 524288u];
        v.w = x[o + 786432u];
        g_rhs[gid] = v;
    }
}

// --- flush one completed row: butterfly reduce + 4 atomics (cold path) ---------
__device__ __forceinline__ void flush_row(unsigned row,
                                          float a0, float a1, float a2, float a3,
                                          unsigned lane,
                                          float* __restrict__ out) {
    #pragma unroll
    for (int d = 16; d > 0; d >>= 1) {
        a0 += __shfl_xor_sync(0xffffffffu, a0, d);
        a1 += __shfl_xor_sync(0xffffffffu, a1, d);
        a2 += __shfl_xor_sync(0xffffffffu, a2, d);
        a3 += __shfl_xor_sync(0xffffffffu, a3, d);
    }
    if (lane < 4u) {
        float s = (lane == 0u) ? a0 : (lane == 1u) ? a1 : (lane == 2u) ? a2 : a3;
        // out layout: bk*131072 + z*256 + x, with row r = x*512 + z
        unsigned o = (row & 511u) * 256u + (row >> 9);
        atomicAdd(out + lane * OUT_PLANE + o, s);
    }
}

// --- main SpMM: each warp owns a contiguous, sorted nnz chunk ------------------
// Depth-1 software pipeline, 32 regs, occ ~81%. Empirical optimum across 8
// structural variants (deeper pipelines, finer grids, balanced waves, ldcs all
// regressed); L1-busy is pinned at the 16.7M gather-wavefront floor (~60us).
__global__ void __launch_bounds__(256)
k_spmm(const float* __restrict__ vals,
       const unsigned* __restrict__ rows_u32,
       const unsigned* __restrict__ cols_u32,
       float* __restrict__ out) {
    const unsigned warp_id = (blockIdx.x * blockDim.x + threadIdx.x) >> 5;
    const unsigned lane    = threadIdx.x & 31u;
    const unsigned st      = g_stride;          // 1 (int32) or 2 (int64, read low word)
    const unsigned base    = warp_id * NNZ_PER_WARP;
    const unsigned rstep   = st * 32u;

    const float*    vp = vals     + base + lane;
    const unsigned* rp = rows_u32 + st * (base + lane);
    const unsigned* cp = cols_u32 + st * (base + lane);

    // pipeline stage 0
    float    v   = *vp;
    unsigned row = *rp;
    unsigned col = *cp;
    float4   r   = g_rhs[col];

    unsigned cur_row = __shfl_sync(0xffffffffu, row, 0);
    float a0 = 0.f, a1 = 0.f, a2 = 0.f, a3 = 0.f;

    #pragma unroll 1
    for (int it = 0; it < ITERS - 1; ++it) {
        // prefetch next iteration (hides gather latency behind the logic below)
        vp += 32u; rp += rstep; cp += rstep;
        float    vn   = *vp;
        unsigned rown = *rp;
        unsigned coln = *cp;
        float4   rn   = g_rhs[coln];

        float c0 = v * r.x, c1 = v * r.y, c2 = v * r.z, c3 = v * r.w;
        if (__all_sync(0xffffffffu, row == cur_row)) {       // fast path (~75%)
            a0 += c0; a1 += c1; a2 += c2; a3 += c3;
        } else {                                             // row boundary in group
            unsigned r31 = __shfl_sync(0xffffffffu, row, 31);
            bool mine = (row == cur_row);                    // sorted -> prefix lanes
            if (mine) { a0 += c0; a1 += c1; a2 += c2; a3 += c3; }
            flush_row(cur_row, a0, a1, a2, a3, lane, out);
            if (!mine && row != r31) {
                // row fully contained inside this group (needs <32 nnz): direct atomics
                unsigned o = (row & 511u) * 256u + (row >> 9);
                atomicAdd(out + o,                  c0);
                atomicAdd(out + OUT_PLANE + o,      c1);
                atomicAdd(out + 2u * OUT_PLANE + o, c2);
                atomicAdd(out + 3u * OUT_PLANE + o, c3);
            }
            bool last = (row == r31);                        // suffix lanes: new row
            a0 = last ? c0 : 0.f;
            a1 = last ? c1 : 0.f;
            a2 = last ? c2 : 0.f;
            a3 = last ? c3 : 0.f;
            cur_row = r31;
        }
        v = vn; row = rown; r = rn;
    }

    // epilogue: process final group
    {
        float c0 = v * r.x, c1 = v * r.y, c2 = v * r.z, c3 = v * r.w;
        if (__all_sync(0xffffffffu, row == cur_row)) {
            a0 += c0; a1 += c1; a2 += c2; a3 += c3;
        } else {
            unsigned r31 = __shfl_sync(0xffffffffu, row, 31);
            bool mine = (row == cur_row);
            if (mine) { a0 += c0; a1 += c1; a2 += c2; a3 += c3; }
            flush_row(cur_row, a0, a1, a2, a3, lane, out);
            if (!mine && row != r31) {
                unsigned o = (row & 511u) * 256u + (row >> 9);
                atomicAdd(out + o,                  c0);
                atomicAdd(out + OUT_PLANE + o,      c1);
                atomicAdd(out + 2u * OUT_PLANE + o, c2);
                atomicAdd(out + 3u * OUT_PLANE + o, c3);
            }
            bool last = (row == r31);
            a0 = last ? c0 : 0.f;
            a1 = last ? c1 : 0.f;
            a2 = last ? c2 : 0.f;
            a3 = last ? c3 : 0.f;
            cur_row = r31;
        }
    }
    flush_row(cur_row, a0, a1, a2, a3, lane, out);
}

extern "C" void kernel_launch(void* const* d_in, const int* in_sizes, int n_in,
                              void* d_out, int out_size) {
    const float*    x    = (const float*)d_in[0];
    const float*    vals = (const float*)d_in[1];
    const unsigned* rows = (const unsigned*)d_in[2];
    const unsigned* cols = (const unsigned*)d_in[3];
    float*          out  = (float*)d_out;

    k_prep<<<OUT_ELEMS / 256, 256>>>(x, rows, out);
    k_spmm<<<TOTAL_WARPS * 32 / 256, 256>>>(vals, rows, cols, out);
}